// round 10
// baseline (speedup 1.0000x reference)
#include <cuda_runtime.h>
#include <cuda_fp16.h>
#include <cstdint>

#define DIN     8192
#define DOUT    8192
#define MR      32
#define KSPLIT  16
#define KRANGE  (DIN / KSPLIT)   // 512
#define KC      64               // k rows per chunk
#define NCHUNKS (KRANGE / KC)    // 8
#define NTILE   128              // n cols per CTA
#define GTHREADS 256

// padded smem row strides (u16 units) -> conflict-free ldmatrix
#define XSTR 72    // 64 k + 8 pad  (144 B)
#define WSTR 136   // 128 n + 8 pad (272 B)

// single-stage tiles + double-buffered raw W (u16 units)
#define XTILE   (MR * XSTR)              // 2304
#define WTILE   (KC * WSTR)              // 8704
#define OFF_XH  0
#define OFF_XL  XTILE
#define OFF_WH  (2 * XTILE)
#define OFF_WL  (2 * XTILE + WTILE)
#define OFF_RAW (2 * XTILE + 2 * WTILE)  // raw fp32 W stages
#define RAWSTG  16384                    // u16 per stage (= 32KB = 64x128 fp32)
#define SMEM_U16 (OFF_RAW + 2 * RAWSTG)  // 54784 u16 = 109568 B

// ---------------- static device scratch (no runtime alloc) ----------------
__device__ uint16_t g_xh[MR * DIN];                 // x hi bf16 [32][8192]
__device__ uint16_t g_xl[MR * DIN];                 // x lo bf16
__device__ float    g_partial[KSPLIT * MR * DOUT];  // split-k partials (16MB)

// ---------------- helpers ----------------
__device__ __forceinline__ uint32_t smem_u32(const void* p) {
    uint32_t a;
    asm("{ .reg .u64 t; cvta.to.shared.u64 t, %1; cvt.u32.u64 %0, t; }" : "=r"(a) : "l"(p));
    return a;
}
// packed bf16x2: lo half = bf16(a), hi half = bf16(b)
__device__ __forceinline__ uint32_t bf16pack(float a, float b) {
    uint32_t r;
    asm("cvt.rn.bf16x2.f32 %0, %1, %2;" : "=r"(r) : "f"(b), "f"(a));
    return r;
}
__device__ __forceinline__ void ldsm4(uint32_t* r, uint32_t addr) {
    asm volatile("ldmatrix.sync.aligned.m8n8.x4.shared.b16 {%0,%1,%2,%3}, [%4];"
        : "=r"(r[0]), "=r"(r[1]), "=r"(r[2]), "=r"(r[3]) : "r"(addr));
}
__device__ __forceinline__ void ldsm4t(uint32_t* r, uint32_t addr) {
    asm volatile("ldmatrix.sync.aligned.m8n8.x4.trans.shared.b16 {%0,%1,%2,%3}, [%4];"
        : "=r"(r[0]), "=r"(r[1]), "=r"(r[2]), "=r"(r[3]) : "r"(addr));
}
__device__ __forceinline__ void mma_bf16(float* d, const uint32_t* a, const uint32_t* b) {
    asm volatile("mma.sync.aligned.m16n8k16.row.col.f32.bf16.bf16.f32 "
        "{%0,%1,%2,%3}, {%4,%5,%6,%7}, {%8,%9}, {%0,%1,%2,%3};"
        : "+f"(d[0]), "+f"(d[1]), "+f"(d[2]), "+f"(d[3])
        : "r"(a[0]), "r"(a[1]), "r"(a[2]), "r"(a[3]), "r"(b[0]), "r"(b[1]));
}

// ---------------------------------------------------------------------------
// Prep: split x fp32 [32][8192] -> bf16 hi + bf16 lo (row-major, same shape)
// ---------------------------------------------------------------------------
__global__ void prep_x_kernel(const float* __restrict__ x) {
    int idx = blockIdx.x * blockDim.x + threadIdx.x;   // float4 index
    float4 v = reinterpret_cast<const float4*>(x)[idx];
    uint32_t h01 = bf16pack(v.x, v.y);
    uint32_t h23 = bf16pack(v.z, v.w);
    float l0 = v.x - __uint_as_float(h01 << 16);
    float l1 = v.y - __uint_as_float(h01 & 0xffff0000u);
    float l2 = v.z - __uint_as_float(h23 << 16);
    float l3 = v.w - __uint_as_float(h23 & 0xffff0000u);
    uint32_t lo01 = bf16pack(l0, l1);
    uint32_t lo23 = bf16pack(l2, l3);
    reinterpret_cast<uint2*>(g_xh)[idx] = make_uint2(h01, h23);
    reinterpret_cast<uint2*>(g_xl)[idx] = make_uint2(lo01, lo23);
}

// ---------------------------------------------------------------------------
// Main: cp.async-staged raw W (distance 2) -> fused Q4_0 dequant -> bf16
// hi/lo smem tiles -> mma.sync. grid = (DOUT/NTILE, KSPLIT), 8 warps.
// Raw stages are thread-private (each lane cp.asyncs exactly the bytes it
// later reads), so cp.async.wait_group alone synchronizes them.
// ---------------------------------------------------------------------------
__global__ void __launch_bounds__(GTHREADS, 2)
gemm_kernel(const float* __restrict__ W) {
    extern __shared__ __align__(16) uint16_t dsm[];

    const int tid  = threadIdx.x;
    const int wid  = tid >> 5;
    const int lane = tid & 31;
    const int n0   = blockIdx.x * NTILE;
    const int ks   = blockIdx.y;
    const int k0   = ks * KRANGE;

    const uint32_t base = smem_u32(dsm);
    const int lrow = lane & 15;
    const int lcol = lane >> 4;
    const int xm   = tid >> 3;    // 0..31
    const int xseg = tid & 7;     // 0..7

    float d[2][2][4];
#pragma unroll
    for (int a = 0; a < 2; a++)
#pragma unroll
        for (int b = 0; b < 2; b++)
#pragma unroll
            for (int j = 0; j < 4; j++) d[a][b][j] = 0.0f;

    // ---- cp.async W chunk kb into raw stage s (rows wid*8..+7, cols lane*4) ----
    auto cp_w = [&](int kb, int s) {
        const float* src = W + (size_t)(kb + wid * 8) * DOUT + n0 + lane * 4;
        uint32_t dst = base + (uint32_t)(OFF_RAW + s * RAWSTG) * 2
                     + (uint32_t)(wid * 8 * 128 + lane * 4) * 4;
#pragma unroll
        for (int r = 0; r < 8; r++)
            asm volatile("cp.async.cg.shared.global [%0], [%1], 16;"
                :: "r"(dst + r * 512), "l"(src + (size_t)r * DOUT));
        asm volatile("cp.async.commit_group;" ::: "memory");
    };

    auto copy_x = [&](int kb) {
        const uint4* srch = reinterpret_cast<const uint4*>(g_xh) + (xm * 1024 + (kb >> 3) + xseg);
        const uint4* srcl = reinterpret_cast<const uint4*>(g_xl) + (xm * 1024 + (kb >> 3) + xseg);
        *reinterpret_cast<uint4*>(dsm + OFF_XH + xm * XSTR + xseg * 8) = *srch;
        *reinterpret_cast<uint4*>(dsm + OFF_XL + xm * XSTR + xseg * 8) = *srcl;
    };

    auto dequant = [&](int s) {
        const uint32_t wh_s = base + (uint32_t)OFF_WH * 2;
        const uint32_t wl_s = base + (uint32_t)OFF_WL * 2;
        const float4* rw = reinterpret_cast<const float4*>(dsm + OFF_RAW + s * RAWSTG)
                         + (wid * 8 * 32 + lane);
#pragma unroll
        for (int r = 0; r < 8; r++) {
            float4 w = rw[r * 32];

            float b = w.x;
            if (fabsf(w.y) > fabsf(b)) b = w.y;
            if (fabsf(w.z) > fabsf(b)) b = w.z;
            if (fabsf(w.w) > fabsf(b)) b = w.w;
#pragma unroll
            for (int off = 1; off <= 4; off <<= 1) {
                float o  = __shfl_xor_sync(0xffffffffu, b, off);
                float ab = fabsf(b), ao = fabsf(o);
                bool keep = (ab > ao) || (ab == ao && (lane & off) == 0);
                b = keep ? b : o;
            }
            float dd    = b * -0.125f;                       // exact /8
            float scale = __half2float(__float2half_rn(dd)); // fp16 round-trip
            float inv   = __frcp_rn(dd);                     // == RN(1/dd)
            float n8s   = scale * -8.0f;

            float t0 = fminf(truncf(fmaf(w.x, inv, 8.5f)), 15.0f);
            float t1 = fminf(truncf(fmaf(w.y, inv, 8.5f)), 15.0f);
            float t2 = fminf(truncf(fmaf(w.z, inv, 8.5f)), 15.0f);
            float t3 = fminf(truncf(fmaf(w.w, inv, 8.5f)), 15.0f);
            float q0 = fmaf(scale, t0, n8s);
            float q1 = fmaf(scale, t1, n8s);
            float q2 = fmaf(scale, t2, n8s);
            float q3 = fmaf(scale, t3, n8s);

            uint32_t h01 = bf16pack(q0, q1);
            uint32_t h23 = bf16pack(q2, q3);
            float l0 = q0 - __uint_as_float(h01 << 16);
            float l1 = q1 - __uint_as_float(h01 & 0xffff0000u);
            float l2 = q2 - __uint_as_float(h23 << 16);
            float l3 = q3 - __uint_as_float(h23 & 0xffff0000u);
            uint32_t lo01 = bf16pack(l0, l1);
            uint32_t lo23 = bf16pack(l2, l3);

            const int kr = wid * 8 + r;
            uint32_t ha = wh_s + (uint32_t)(kr * WSTR + lane * 4) * 2;
            uint32_t la = wl_s + (uint32_t)(kr * WSTR + lane * 4) * 2;
            asm volatile("st.shared.v2.b32 [%0], {%1,%2};" :: "r"(ha), "r"(h01), "r"(h23) : "memory");
            asm volatile("st.shared.v2.b32 [%0], {%1,%2};" :: "r"(la), "r"(lo01), "r"(lo23) : "memory");
        }
    };

    auto do_mma = [&]() {
        const uint32_t xh_s = base + (uint32_t)OFF_XH * 2;
        const uint32_t xl_s = base + (uint32_t)OFF_XL * 2;
        const uint32_t wh_s = base + (uint32_t)OFF_WH * 2;
        const uint32_t wl_s = base + (uint32_t)OFF_WL * 2;
#pragma unroll
        for (int ksi = 0; ksi < 4; ksi++) {
            uint32_t ah0[4], ah1[4], al0[4], al1[4], bh[4], bl[4];
            uint32_t arow = (uint32_t)(lrow * XSTR + ksi * 16 + lcol * 8) * 2;
            ldsm4(ah0, xh_s + arow);
            ldsm4(ah1, xh_s + arow + 16u * XSTR * 2);
            ldsm4(al0, xl_s + arow);
            ldsm4(al1, xl_s + arow + 16u * XSTR * 2);

            uint32_t brow = (uint32_t)((ksi * 16 + lrow) * WSTR + wid * 16 + lcol * 8) * 2;
            ldsm4t(bh, wh_s + brow);
            ldsm4t(bl, wl_s + brow);

            mma_bf16(d[0][0], ah0, bh);     mma_bf16(d[0][1], ah0, bh + 2);
            mma_bf16(d[1][0], ah1, bh);     mma_bf16(d[1][1], ah1, bh + 2);
            mma_bf16(d[0][0], ah0, bl);     mma_bf16(d[0][1], ah0, bl + 2);
            mma_bf16(d[1][0], ah1, bl);     mma_bf16(d[1][1], ah1, bl + 2);
            mma_bf16(d[0][0], al0, bh);     mma_bf16(d[0][1], al0, bh + 2);
            mma_bf16(d[1][0], al1, bh);     mma_bf16(d[1][1], al1, bh + 2);
        }
    };

    // ---- prolog: raw stages 0 and 1 in flight (groups 0, 1) ----
    cp_w(k0, 0);
    cp_w(k0 + KC, 1);

#pragma unroll 1
    for (int c = 0; c < NCHUNKS; c++) {
        const int s = c & 1;
        // group c must be complete (<=1 newer group outstanding)
        asm volatile("cp.async.wait_group 1;" ::: "memory");
        __syncthreads();                       // mma(c-1) done before tile overwrite
        copy_x(k0 + c * KC);
        dequant(s);                            // reads raw[s] (thread-private bytes)
        if (c + 2 < NCHUNKS) cp_w(k0 + (c + 2) * KC, s);
        else asm volatile("cp.async.commit_group;" ::: "memory");   // empty group
        __syncthreads();                       // tiles ready
        do_mma();
    }

    // ---- write split-k partials ----
    {
        const int g4   = lane >> 2;
        const int tid4 = lane & 3;
        float* obase = g_partial + (size_t)ks * MR * DOUT + n0 + wid * 16;
#pragma unroll
        for (int mt = 0; mt < 2; mt++) {
#pragma unroll
            for (int nt = 0; nt < 2; nt++) {
                int col = nt * 8 + tid4 * 2;
                float* p0 = obase + (size_t)(mt * 16 + g4)     * DOUT + col;
                float* p1 = obase + (size_t)(mt * 16 + g4 + 8) * DOUT + col;
                *reinterpret_cast<float2*>(p0) = make_float2(d[mt][nt][0], d[mt][nt][1]);
                *reinterpret_cast<float2*>(p1) = make_float2(d[mt][nt][2], d[mt][nt][3]);
            }
        }
    }
}

// ---------------------------------------------------------------------------
// Epilog: out = bias + sum_ks partials
// ---------------------------------------------------------------------------
__global__ void reduce_kernel(const float* __restrict__ bias, float* __restrict__ out) {
    int i = blockIdx.x * blockDim.x + threadIdx.x;   // float4 index
    if (i >= (MR * DOUT) / 4) return;
    int n4 = i & (DOUT / 4 - 1);
    float4 s = reinterpret_cast<const float4*>(bias)[n4];
#pragma unroll
    for (int k = 0; k < KSPLIT; k++) {
        float4 p = reinterpret_cast<const float4*>(g_partial + (size_t)k * MR * DOUT)[i];
        s.x += p.x; s.y += p.y; s.z += p.z; s.w += p.w;
    }
    reinterpret_cast<float4*>(out)[i] = s;
}

// ---------------------------------------------------------------------------
extern "C" void kernel_launch(void* const* d_in, const int* in_sizes, int n_in,
                              void* d_out, int out_size) {
    const float *X = nullptr, *W = nullptr, *B = nullptr;
    for (int i = 0; i < n_in; i++) {
        long long sz = in_sizes[i];
        if      (sz == (long long)DIN * DOUT) W = (const float*)d_in[i];
        else if (sz == (long long)MR * DIN)   X = (const float*)d_in[i];
        else if (sz == (long long)DOUT)       B = (const float*)d_in[i];
    }

    const int smem_bytes = SMEM_U16 * 2;   // 109568 B
    cudaFuncSetAttribute(gemm_kernel, cudaFuncAttributeMaxDynamicSharedMemorySize, smem_bytes);

    prep_x_kernel<<<(MR * DIN / 4) / 256, 256>>>(X);

    dim3 grid(DOUT / NTILE, KSPLIT);   // 64 x 16 = 1024 CTAs
    gemm_kernel<<<grid, GTHREADS, smem_bytes>>>(W);

    reduce_kernel<<<(MR * DOUT / 4 + 255) / 256, 256>>>(B, (float*)d_out);
}

// round 11
// speedup vs baseline: 1.5424x; 1.5424x over previous
#include <cuda_runtime.h>
#include <cuda_fp16.h>
#include <cstdint>

#define DIN     8192
#define DOUT    8192
#define MR      32
#define KSPLIT  8
#define KRANGE  (DIN / KSPLIT)   // 1024
#define KC      64               // k rows per chunk
#define NCHUNKS (KRANGE / KC)    // 16
#define NTILE   128              // n cols per CTA
#define GTHREADS 256

// padded smem row strides (u16 units) -> conflict-free ldmatrix
#define XSTR 72    // 64 k + 8 pad  (144 B)
#define WSTR 136   // 128 n + 8 pad (272 B)

// ---------------- static device scratch (no runtime alloc) ----------------
__device__ uint16_t g_xh[MR * DIN];                 // x fp16 [32][8192] (512KB)
__device__ float    g_partial[KSPLIT * MR * DOUT];  // split-k partials (8MB)

// ---------------- helpers ----------------
__device__ __forceinline__ uint32_t smem_u32(const void* p) {
    uint32_t a;
    asm("{ .reg .u64 t; cvta.to.shared.u64 t, %1; cvt.u32.u64 %0, t; }" : "=r"(a) : "l"(p));
    return a;
}
// packed fp16x2: lo half = f16(a), hi half = f16(b)
__device__ __forceinline__ uint32_t f16pack(float a, float b) {
    __half2 h = __floats2half2_rn(a, b);
    return *reinterpret_cast<uint32_t*>(&h);
}
__device__ __forceinline__ float f16lo(uint32_t v) {
    __half h = *reinterpret_cast<__half*>(&v);
    return __half2float(h);
}
__device__ __forceinline__ float f16hi(uint32_t v) {
    uint16_t u = (uint16_t)(v >> 16);
    __half h = *reinterpret_cast<__half*>(&u);
    return __half2float(h);
}
__device__ __forceinline__ void ldsm4(uint32_t* r, uint32_t addr) {
    asm volatile("ldmatrix.sync.aligned.m8n8.x4.shared.b16 {%0,%1,%2,%3}, [%4];"
        : "=r"(r[0]), "=r"(r[1]), "=r"(r[2]), "=r"(r[3]) : "r"(addr));
}
__device__ __forceinline__ void ldsm4t(uint32_t* r, uint32_t addr) {
    asm volatile("ldmatrix.sync.aligned.m8n8.x4.trans.shared.b16 {%0,%1,%2,%3}, [%4];"
        : "=r"(r[0]), "=r"(r[1]), "=r"(r[2]), "=r"(r[3]) : "r"(addr));
}
__device__ __forceinline__ void mma_f16(float* d, const uint32_t* a, const uint32_t* b) {
    asm volatile("mma.sync.aligned.m16n8k16.row.col.f32.f16.f16.f32 "
        "{%0,%1,%2,%3}, {%4,%5,%6,%7}, {%8,%9}, {%0,%1,%2,%3};"
        : "+f"(d[0]), "+f"(d[1]), "+f"(d[2]), "+f"(d[3])
        : "r"(a[0]), "r"(a[1]), "r"(a[2]), "r"(a[3]), "r"(b[0]), "r"(b[1]));
}

// ---------------------------------------------------------------------------
// Prep: x fp32 [32][8192] -> fp16 (row-major, same shape)
// ---------------------------------------------------------------------------
__global__ void prep_x_kernel(const float* __restrict__ x) {
    int idx = blockIdx.x * blockDim.x + threadIdx.x;   // float4 index
    float4 v = reinterpret_cast<const float4*>(x)[idx];
    reinterpret_cast<uint2*>(g_xh)[idx] =
        make_uint2(f16pack(v.x, v.y), f16pack(v.z, v.w));
}

// ---------------------------------------------------------------------------
// Main: fused Q4_0 dequant -> fp16 w hi/lo smem tiles + fp16 x -> mma.sync.
// 2-term: y = x_h*(w_h + w_l); w_h+w_l is exact to 2^-24, x fp16 adds ~2^-12.
// grid = (DOUT/NTILE, KSPLIT), 8 warps. R6 structure (the 96.8us winner):
// LDG->reg W with front-batched MLP=8, single-stage tiles, 2 barriers/chunk.
// ---------------------------------------------------------------------------
__global__ void __launch_bounds__(GTHREADS, 2)
gemm_kernel(const float* __restrict__ W) {
    __shared__ __align__(16) uint16_t sXH[MR * XSTR];   // 4.5 KB
    __shared__ __align__(16) uint16_t sWH[KC * WSTR];   // 17 KB
    __shared__ __align__(16) uint16_t sWL[KC * WSTR];   // 17 KB

    const int tid  = threadIdx.x;
    const int wid  = tid >> 5;
    const int lane = tid & 31;
    const int n0   = blockIdx.x * NTILE;
    const int ks   = blockIdx.y;
    const int k0   = ks * KRANGE;

    const uint32_t xh_s = smem_u32(sXH);
    const uint32_t wh_s = smem_u32(sWH);
    const uint32_t wl_s = smem_u32(sWL);

    const int lrow = lane & 15;
    const int lcol = lane >> 4;
    const int xm   = tid >> 3;    // 0..31
    const int xseg = tid & 7;     // 0..7  (x row = 8 segments of 8B fp16)

    float d[2][2][4];
#pragma unroll
    for (int a = 0; a < 2; a++)
#pragma unroll
        for (int b = 0; b < 2; b++)
#pragma unroll
            for (int j = 0; j < 4; j++) d[a][b][j] = 0.0f;

    // front-batched W prefetch for chunk 0 (8 x LDG.128, MLP=8)
    float4 wv[8];
#pragma unroll
    for (int r = 0; r < 8; r++)
        wv[r] = reinterpret_cast<const float4*>(
            W + (size_t)(k0 + wid * 8 + r) * DOUT + n0)[lane];

#pragma unroll 1
    for (int c = 0; c < NCHUNKS; c++) {
        const int kb = k0 + c * KC;

        // ---- copy x chunk (pre-converted fp16): 64 k = 128 B/row, 8B segs ----
        {
            const uint2* src = reinterpret_cast<const uint2*>(g_xh)
                             + (xm * 2048 + (kb >> 2) + xseg * 2);   // uint2 = 4 fp16
            uint2 v0 = src[0], v1 = src[1];
            *reinterpret_cast<uint4*>(sXH + xm * XSTR + xseg * 8) =
                make_uint4(v0.x, v0.y, v1.x, v1.y);
        }

        // ---- dequant 8 k-rows per warp -> fp16 w hi/lo smem ----
#pragma unroll
        for (int r = 0; r < 8; r++) {
            float4 w = wv[r];

            // abs-argmax (signed value) over the 32-wide n block (8 lanes)
            float b = w.x;
            if (fabsf(w.y) > fabsf(b)) b = w.y;
            if (fabsf(w.z) > fabsf(b)) b = w.z;
            if (fabsf(w.w) > fabsf(b)) b = w.w;
#pragma unroll
            for (int off = 1; off <= 4; off <<= 1) {
                float o  = __shfl_xor_sync(0xffffffffu, b, off);
                float ab = fabsf(b), ao = fabsf(o);
                bool keep = (ab > ao) || (ab == ao && (lane & off) == 0);
                b = keep ? b : o;
            }
            float dd    = b * -0.125f;                       // exact /8
            float scale = __half2float(__float2half_rn(dd)); // fp16 round-trip
            float inv   = __frcp_rn(dd);                     // == RN(1/dd)
            float n8s   = scale * -8.0f;

            float t0 = fminf(truncf(fmaf(w.x, inv, 8.5f)), 15.0f);
            float t1 = fminf(truncf(fmaf(w.y, inv, 8.5f)), 15.0f);
            float t2 = fminf(truncf(fmaf(w.z, inv, 8.5f)), 15.0f);
            float t3 = fminf(truncf(fmaf(w.w, inv, 8.5f)), 15.0f);
            float q0 = fmaf(scale, t0, n8s);
            float q1 = fmaf(scale, t1, n8s);
            float q2 = fmaf(scale, t2, n8s);
            float q3 = fmaf(scale, t3, n8s);

            // fp16 hi/lo split (w_h + w_l == w to 2^-24)
            uint32_t h01 = f16pack(q0, q1);
            uint32_t h23 = f16pack(q2, q3);
            uint32_t l01 = f16pack(q0 - f16lo(h01), q1 - f16hi(h01));
            uint32_t l23 = f16pack(q2 - f16lo(h23), q3 - f16hi(h23));

            const int kr = wid * 8 + r;
            uint32_t ha = wh_s + (uint32_t)(kr * WSTR + lane * 4) * 2;
            uint32_t la = wl_s + (uint32_t)(kr * WSTR + lane * 4) * 2;
            asm volatile("st.shared.v2.b32 [%0], {%1,%2};" :: "r"(ha), "r"(h01), "r"(h23) : "memory");
            asm volatile("st.shared.v2.b32 [%0], {%1,%2};" :: "r"(la), "r"(l01), "r"(l23) : "memory");
        }

        // ---- prefetch next chunk's W (hidden behind mma + barriers) ----
        if (c + 1 < NCHUNKS) {
            const int kb2 = kb + KC;
#pragma unroll
            for (int r = 0; r < 8; r++)
                wv[r] = reinterpret_cast<const float4*>(
                    W + (size_t)(kb2 + wid * 8 + r) * DOUT + n0)[lane];
        }

        __syncthreads();

        // ---- mma: warp owns n slice [wid*16, wid*16+16), 2 terms ----
#pragma unroll
        for (int ksi = 0; ksi < 4; ksi++) {
            uint32_t ah0[4], ah1[4], bh[4], bl[4];
            uint32_t arow = (uint32_t)(lrow * XSTR + ksi * 16 + lcol * 8) * 2;
            ldsm4(ah0, xh_s + arow);                       // m 0..15
            ldsm4(ah1, xh_s + arow + 16u * XSTR * 2);      // m 16..31

            uint32_t brow = (uint32_t)((ksi * 16 + lrow) * WSTR + wid * 16 + lcol * 8) * 2;
            ldsm4t(bh, wh_s + brow);
            ldsm4t(bl, wl_s + brow);

            mma_f16(d[0][0], ah0, bh);     mma_f16(d[0][1], ah0, bh + 2);
            mma_f16(d[1][0], ah1, bh);     mma_f16(d[1][1], ah1, bh + 2);
            mma_f16(d[0][0], ah0, bl);     mma_f16(d[0][1], ah0, bl + 2);
            mma_f16(d[1][0], ah1, bl);     mma_f16(d[1][1], ah1, bl + 2);
        }
        __syncthreads();
    }

    // ---- write split-k partials ----
    {
        const int g4   = lane >> 2;
        const int tid4 = lane & 3;
        float* obase = g_partial + (size_t)ks * MR * DOUT + n0 + wid * 16;
#pragma unroll
        for (int mt = 0; mt < 2; mt++) {
#pragma unroll
            for (int nt = 0; nt < 2; nt++) {
                int col = nt * 8 + tid4 * 2;
                float* p0 = obase + (size_t)(mt * 16 + g4)     * DOUT + col;
                float* p1 = obase + (size_t)(mt * 16 + g4 + 8) * DOUT + col;
                *reinterpret_cast<float2*>(p0) = make_float2(d[mt][nt][0], d[mt][nt][1]);
                *reinterpret_cast<float2*>(p1) = make_float2(d[mt][nt][2], d[mt][nt][3]);
            }
        }
    }
}

// ---------------------------------------------------------------------------
// Epilog: out = bias + sum_ks partials
// ---------------------------------------------------------------------------
__global__ void reduce_kernel(const float* __restrict__ bias, float* __restrict__ out) {
    int i = blockIdx.x * blockDim.x + threadIdx.x;   // float4 index
    if (i >= (MR * DOUT) / 4) return;
    int n4 = i & (DOUT / 4 - 1);
    float4 s = reinterpret_cast<const float4*>(bias)[n4];
#pragma unroll
    for (int k = 0; k < KSPLIT; k++) {
        float4 p = reinterpret_cast<const float4*>(g_partial + (size_t)k * MR * DOUT)[i];
        s.x += p.x; s.y += p.y; s.z += p.z; s.w += p.w;
    }
    reinterpret_cast<float4*>(out)[i] = s;
}

// ---------------------------------------------------------------------------
extern "C" void kernel_launch(void* const* d_in, const int* in_sizes, int n_in,
                              void* d_out, int out_size) {
    const float *X = nullptr, *W = nullptr, *B = nullptr;
    for (int i = 0; i < n_in; i++) {
        long long sz = in_sizes[i];
        if      (sz == (long long)DIN * DOUT) W = (const float*)d_in[i];
        else if (sz == (long long)MR * DIN)   X = (const float*)d_in[i];
        else if (sz == (long long)DOUT)       B = (const float*)d_in[i];
    }

    prep_x_kernel<<<(MR * DIN / 4) / 256, 256>>>(X);

    dim3 grid(DOUT / NTILE, KSPLIT);   // 64 x 8 = 512 CTAs
    gemm_kernel<<<grid, GTHREADS>>>(W);

    reduce_kernel<<<(MR * DOUT / 4 + 255) / 256, 256>>>(B, (float*)d_out);
}

// round 12
// speedup vs baseline: 1.6495x; 1.0695x over previous
#include <cuda_runtime.h>
#include <cuda_fp16.h>
#include <cstdint>

#define DIN     8192
#define DOUT    8192
#define MR      32
#define KSPLIT  8
#define KRANGE  (DIN / KSPLIT)   // 1024
#define KC      64               // k rows per chunk
#define NCHUNKS (KRANGE / KC)    // 16
#define NTILE   128              // n cols per CTA
#define GTHREADS 256

// padded smem row strides (u16 units) -> conflict-free ldmatrix
#define XSTR 72    // 64 k + 8 pad  (144 B)
#define WSTR 136   // 128 n + 8 pad (272 B)

// ---------------- static device scratch (no runtime alloc) ----------------
__device__ uint16_t g_xh[MR * DIN];                 // x fp16 [32][8192] (512KB)
__device__ float    g_partial[KSPLIT * MR * DOUT];  // split-k partials (8MB)

// ---------------- helpers ----------------
__device__ __forceinline__ uint32_t smem_u32(const void* p) {
    uint32_t a;
    asm("{ .reg .u64 t; cvta.to.shared.u64 t, %1; cvt.u32.u64 %0, t; }" : "=r"(a) : "l"(p));
    return a;
}
// packed fp16x2: lo half = f16(a), hi half = f16(b)
__device__ __forceinline__ uint32_t f16pack(float a, float b) {
    __half2 h = __floats2half2_rn(a, b);
    return *reinterpret_cast<uint32_t*>(&h);
}
__device__ __forceinline__ void ldsm4(uint32_t* r, uint32_t addr) {
    asm volatile("ldmatrix.sync.aligned.m8n8.x4.shared.b16 {%0,%1,%2,%3}, [%4];"
        : "=r"(r[0]), "=r"(r[1]), "=r"(r[2]), "=r"(r[3]) : "r"(addr));
}
__device__ __forceinline__ void ldsm4t(uint32_t* r, uint32_t addr) {
    asm volatile("ldmatrix.sync.aligned.m8n8.x4.trans.shared.b16 {%0,%1,%2,%3}, [%4];"
        : "=r"(r[0]), "=r"(r[1]), "=r"(r[2]), "=r"(r[3]) : "r"(addr));
}
__device__ __forceinline__ void mma_f16(float* d, const uint32_t* a, const uint32_t* b) {
    asm volatile("mma.sync.aligned.m16n8k16.row.col.f32.f16.f16.f32 "
        "{%0,%1,%2,%3}, {%4,%5,%6,%7}, {%8,%9}, {%0,%1,%2,%3};"
        : "+f"(d[0]), "+f"(d[1]), "+f"(d[2]), "+f"(d[3])
        : "r"(a[0]), "r"(a[1]), "r"(a[2]), "r"(a[3]), "r"(b[0]), "r"(b[1]));
}

// ---------------------------------------------------------------------------
// Prep: x fp32 [32][8192] -> fp16 (row-major, same shape)
// ---------------------------------------------------------------------------
__global__ void prep_x_kernel(const float* __restrict__ x) {
    int idx = blockIdx.x * blockDim.x + threadIdx.x;   // float4 index
    float4 v = reinterpret_cast<const float4*>(x)[idx];
    reinterpret_cast<uint2*>(g_xh)[idx] =
        make_uint2(f16pack(v.x, v.y), f16pack(v.z, v.w));
}

// ---------------------------------------------------------------------------
// Main: fused Q4_0 dequant -> fp16 w smem tile + fp16 x -> mma.sync.
// Single-term: y = x_f16 * w_f16 (each ~2^-12 rounding; combined ~3e-4).
// grid = (DOUT/NTILE, KSPLIT), 8 warps, R6 loop structure.
// ---------------------------------------------------------------------------
__global__ void __launch_bounds__(GTHREADS, 2)
gemm_kernel(const float* __restrict__ W) {
    __shared__ __align__(16) uint16_t sXH[MR * XSTR];   // 4.5 KB
    __shared__ __align__(16) uint16_t sWH[KC * WSTR];   // 17 KB

    const int tid  = threadIdx.x;
    const int wid  = tid >> 5;
    const int lane = tid & 31;
    const int n0   = blockIdx.x * NTILE;
    const int ks   = blockIdx.y;
    const int k0   = ks * KRANGE;

    const uint32_t xh_s = smem_u32(sXH);
    const uint32_t wh_s = smem_u32(sWH);

    const int lrow = lane & 15;
    const int lcol = lane >> 4;
    const int xm   = tid >> 3;    // 0..31
    const int xseg = tid & 7;     // 0..7

    float d[2][2][4];
#pragma unroll
    for (int a = 0; a < 2; a++)
#pragma unroll
        for (int b = 0; b < 2; b++)
#pragma unroll
            for (int j = 0; j < 4; j++) d[a][b][j] = 0.0f;

    // front-batched W prefetch for chunk 0 (8 x LDG.128, MLP=8)
    float4 wv[8];
#pragma unroll
    for (int r = 0; r < 8; r++)
        wv[r] = reinterpret_cast<const float4*>(
            W + (size_t)(k0 + wid * 8 + r) * DOUT + n0)[lane];

#pragma unroll 1
    for (int c = 0; c < NCHUNKS; c++) {
        const int kb = k0 + c * KC;

        // ---- copy x chunk (pre-converted fp16): 64 k = 128 B/row ----
        {
            const uint2* src = reinterpret_cast<const uint2*>(g_xh)
                             + (xm * 2048 + (kb >> 2) + xseg * 2);
            uint2 v0 = src[0], v1 = src[1];
            *reinterpret_cast<uint4*>(sXH + xm * XSTR + xseg * 8) =
                make_uint4(v0.x, v0.y, v1.x, v1.y);
        }

        // ---- dequant 8 k-rows per warp -> fp16 w smem ----
#pragma unroll
        for (int r = 0; r < 8; r++) {
            float4 w = wv[r];

            // abs-argmax (signed value) over the 32-wide n block (8 lanes)
            float b = w.x;
            if (fabsf(w.y) > fabsf(b)) b = w.y;
            if (fabsf(w.z) > fabsf(b)) b = w.z;
            if (fabsf(w.w) > fabsf(b)) b = w.w;
#pragma unroll
            for (int off = 1; off <= 4; off <<= 1) {
                float o  = __shfl_xor_sync(0xffffffffu, b, off);
                float ab = fabsf(b), ao = fabsf(o);
                bool keep = (ab > ao) || (ab == ao && (lane & off) == 0);
                b = keep ? b : o;
            }
            float dd    = b * -0.125f;                       // exact /8
            float scale = __half2float(__float2half_rn(dd)); // fp16 round-trip
            float inv   = __frcp_rn(dd);                     // == RN(1/dd)
            float n8s   = scale * -8.0f;

            float t0 = fminf(truncf(fmaf(w.x, inv, 8.5f)), 15.0f);
            float t1 = fminf(truncf(fmaf(w.y, inv, 8.5f)), 15.0f);
            float t2 = fminf(truncf(fmaf(w.z, inv, 8.5f)), 15.0f);
            float t3 = fminf(truncf(fmaf(w.w, inv, 8.5f)), 15.0f);
            float q0 = fmaf(scale, t0, n8s);
            float q1 = fmaf(scale, t1, n8s);
            float q2 = fmaf(scale, t2, n8s);
            float q3 = fmaf(scale, t3, n8s);

            uint32_t h01 = f16pack(q0, q1);
            uint32_t h23 = f16pack(q2, q3);

            const int kr = wid * 8 + r;
            uint32_t ha = wh_s + (uint32_t)(kr * WSTR + lane * 4) * 2;
            asm volatile("st.shared.v2.b32 [%0], {%1,%2};" :: "r"(ha), "r"(h01), "r"(h23) : "memory");
        }

        // ---- prefetch next chunk's W (hidden behind mma + barriers) ----
        if (c + 1 < NCHUNKS) {
            const int kb2 = kb + KC;
#pragma unroll
            for (int r = 0; r < 8; r++)
                wv[r] = reinterpret_cast<const float4*>(
                    W + (size_t)(kb2 + wid * 8 + r) * DOUT + n0)[lane];
        }

        __syncthreads();

        // ---- mma: warp owns n slice [wid*16, wid*16+16), single term ----
#pragma unroll
        for (int ksi = 0; ksi < 4; ksi++) {
            uint32_t ah0[4], ah1[4], bh[4];
            uint32_t arow = (uint32_t)(lrow * XSTR + ksi * 16 + lcol * 8) * 2;
            ldsm4(ah0, xh_s + arow);                       // m 0..15
            ldsm4(ah1, xh_s + arow + 16u * XSTR * 2);      // m 16..31

            uint32_t brow = (uint32_t)((ksi * 16 + lrow) * WSTR + wid * 16 + lcol * 8) * 2;
            ldsm4t(bh, wh_s + brow);

            mma_f16(d[0][0], ah0, bh);     mma_f16(d[0][1], ah0, bh + 2);
            mma_f16(d[1][0], ah1, bh);     mma_f16(d[1][1], ah1, bh + 2);
        }
        __syncthreads();
    }

    // ---- write split-k partials ----
    {
        const int g4   = lane >> 2;
        const int tid4 = lane & 3;
        float* obase = g_partial + (size_t)ks * MR * DOUT + n0 + wid * 16;
#pragma unroll
        for (int mt = 0; mt < 2; mt++) {
#pragma unroll
            for (int nt = 0; nt < 2; nt++) {
                int col = nt * 8 + tid4 * 2;
                float* p0 = obase + (size_t)(mt * 16 + g4)     * DOUT + col;
                float* p1 = obase + (size_t)(mt * 16 + g4 + 8) * DOUT + col;
                *reinterpret_cast<float2*>(p0) = make_float2(d[mt][nt][0], d[mt][nt][1]);
                *reinterpret_cast<float2*>(p1) = make_float2(d[mt][nt][2], d[mt][nt][3]);
            }
        }
    }
}

// ---------------------------------------------------------------------------
// Epilog: out = bias + sum_ks partials
// ---------------------------------------------------------------------------
__global__ void reduce_kernel(const float* __restrict__ bias, float* __restrict__ out) {
    int i = blockIdx.x * blockDim.x + threadIdx.x;   // float4 index
    if (i >= (MR * DOUT) / 4) return;
    int n4 = i & (DOUT / 4 - 1);
    float4 s = reinterpret_cast<const float4*>(bias)[n4];
#pragma unroll
    for (int k = 0; k < KSPLIT; k++) {
        float4 p = reinterpret_cast<const float4*>(g_partial + (size_t)k * MR * DOUT)[i];
        s.x += p.x; s.y += p.y; s.z += p.z; s.w += p.w;
    }
    reinterpret_cast<float4*>(out)[i] = s;
}

// ---------------------------------------------------------------------------
extern "C" void kernel_launch(void* const* d_in, const int* in_sizes, int n_in,
                              void* d_out, int out_size) {
    const float *X = nullptr, *W = nullptr, *B = nullptr;
    for (int i = 0; i < n_in; i++) {
        long long sz = in_sizes[i];
        if      (sz == (long long)DIN * DOUT) W = (const float*)d_in[i];
        else if (sz == (long long)MR * DIN)   X = (const float*)d_in[i];
        else if (sz == (long long)DOUT)       B = (const float*)d_in[i];
    }

    prep_x_kernel<<<(MR * DIN / 4) / 256, 256>>>(X);

    dim3 grid(DOUT / NTILE, KSPLIT);   // 64 x 8 = 512 CTAs
    gemm_kernel<<<grid, GTHREADS>>>(W);

    reduce_kernel<<<(MR * DOUT / 4 + 255) / 256, 256>>>(B, (float*)d_out);
}